// round 4
// baseline (speedup 1.0000x reference)
#include <cuda_runtime.h>

#define B_TOT 8192
#define N_NET 722
#define CAMD  10
#define IND   11
#define HD    10
#define LODD  6

using u64 = unsigned long long;

static __device__ __forceinline__ u64 pk2(float a, float b) {
    u64 r; asm("mov.b64 %0, {%1, %2};" : "=l"(r) : "f"(a), "f"(b)); return r;
}
static __device__ __forceinline__ void unpk2(u64 v, float& a, float& b) {
    asm("mov.b64 {%0, %1}, %2;" : "=f"(a), "=f"(b) : "l"(v));
}
// Packed 2-wide fp32 FMA (Blackwell FFMA2) — only reachable via PTX.
static __device__ __forceinline__ u64 ffma2(u64 a, u64 b, u64 c) {
    u64 d; asm("fma.rn.f32x2 %0, %1, %2, %3;" : "=l"(d) : "l"(a), "l"(b), "l"(c)); return d;
}
static __device__ __forceinline__ u64 relu2(u64 v) {
    float a, b; unpk2(v, a, b);
    a = fmaxf(a, 0.0f); b = fmaxf(b, 0.0f);
    return pk2(a, b);
}

// One block: one network n. 256 threads, 1 f32x2 pair (2 batch rows) per thread,
// looping over 2 batch tiles of 512 rows => 1024 rows/block.
// Low register count (target <=64) => 4 blocks/SM => 32 warps (50% occ) to hide
// LDS(29cyc)/FFMA(4cyc) latency. Weights in smem pre-duplicated (w,w) so one
// broadcast LDS.64 feeds an FFMA2 directly.
__global__ __launch_bounds__(256, 4) void mlp_kernel(
    const float* __restrict__ prior,  // [B, N]
    const float* __restrict__ cam,    // [B, CAM]
    const float* __restrict__ W1,     // [N, IN, H]
    const float* __restrict__ b1,     // [N, H]
    const float* __restrict__ W2,     // [N, H, H]
    const float* __restrict__ b2,     // [N, H]
    const float* __restrict__ W3,     // [N, H, LOD]
    const float* __restrict__ b3,     // [N, LOD]
    float* __restrict__ out)          // [B, N, LOD]
{
    __shared__ u64 s_w1[IND * HD];
    __shared__ u64 s_b1[HD];
    __shared__ u64 s_w2[HD * HD];
    __shared__ u64 s_b2[HD];
    __shared__ u64 s_w3[HD * LODD];
    __shared__ u64 s_b3[LODD];

    const int n   = blockIdx.x;
    const int tid = threadIdx.x;

    // Cooperative weight stage, duplicated into both f32x2 halves.
    for (int i = tid; i < IND * HD; i += 256) { float v = W1[n * IND * HD + i]; s_w1[i] = pk2(v, v); }
    for (int i = tid; i < HD * HD;  i += 256) { float v = W2[n * HD * HD + i];  s_w2[i] = pk2(v, v); }
    for (int i = tid; i < HD * LODD; i += 256){ float v = W3[n * HD * LODD + i]; s_w3[i] = pk2(v, v); }
    if (tid < HD) {
        float v = b1[n * HD + tid]; s_b1[tid] = pk2(v, v);
        v       = b2[n * HD + tid]; s_b2[tid] = pk2(v, v);
    }
    if (tid < LODD) { float v = b3[n * LODD + tid]; s_b3[tid] = pk2(v, v); }
    __syncthreads();

#pragma unroll 1
    for (int it = 0; it < 2; it++) {
        const int b0 = (blockIdx.y * 2 + it) * 512 + tid * 2;  // 2 consecutive rows
        const int b1r = b0 + 1;

        // Pack inputs: x[i] = (x_{b0}, x_{b0+1})
        u64 x[IND];
        x[0] = pk2(prior[(size_t)b0 * N_NET + n], prior[(size_t)b1r * N_NET + n]);
        {
            const float2* ca = reinterpret_cast<const float2*>(cam + (size_t)b0 * CAMD);
            const float2* cb = reinterpret_cast<const float2*>(cam + (size_t)b1r * CAMD);
#pragma unroll
            for (int c = 0; c < 5; c++) {
                float2 va = ca[c], vb = cb[c];
                x[1 + 2 * c] = pk2(va.x, vb.x);
                x[2 + 2 * c] = pk2(va.y, vb.y);
            }
        }

        // ---- Layer 1: [IN=11] -> [H=10], ReLU ----
        u64 h1[HD];
#pragma unroll
        for (int h = 0; h < HD; h++) h1[h] = s_b1[h];
#pragma unroll
        for (int i = 0; i < IND; i++) {
#pragma unroll
            for (int h = 0; h < HD; h++)
                h1[h] = ffma2(x[i], s_w1[i * HD + h], h1[h]);
        }
#pragma unroll
        for (int h = 0; h < HD; h++) h1[h] = relu2(h1[h]);

        // ---- Layer 2: [H=10] -> [H=10], ReLU ----
        u64 h2[HD];
#pragma unroll
        for (int k = 0; k < HD; k++) h2[k] = s_b2[k];
#pragma unroll
        for (int h = 0; h < HD; h++) {
#pragma unroll
            for (int k = 0; k < HD; k++)
                h2[k] = ffma2(h1[h], s_w2[h * HD + k], h2[k]);
        }
#pragma unroll
        for (int k = 0; k < HD; k++) h2[k] = relu2(h2[k]);

        // ---- Layer 3: [H=10] -> [LOD=6] ----
        u64 o[LODD];
#pragma unroll
        for (int l = 0; l < LODD; l++) o[l] = s_b3[l];
#pragma unroll
        for (int h = 0; h < HD; h++) {
#pragma unroll
            for (int l = 0; l < LODD; l++)
                o[l] = ffma2(h2[h], s_w3[h * LODD + l], o[l]);
        }

        // ---- Store: out[b][n][0..5] = 24B, 8B-aligned -> 3x st.64 per row ----
        float oa[LODD], ob[LODD];
#pragma unroll
        for (int l = 0; l < LODD; l++) unpk2(o[l], oa[l], ob[l]);
        float2* pa = reinterpret_cast<float2*>(out + ((size_t)b0  * N_NET + n) * LODD);
        float2* pb = reinterpret_cast<float2*>(out + ((size_t)b1r * N_NET + n) * LODD);
        pa[0] = make_float2(oa[0], oa[1]);
        pa[1] = make_float2(oa[2], oa[3]);
        pa[2] = make_float2(oa[4], oa[5]);
        pb[0] = make_float2(ob[0], ob[1]);
        pb[1] = make_float2(ob[2], ob[3]);
        pb[2] = make_float2(ob[4], ob[5]);
    }
}

extern "C" void kernel_launch(void* const* d_in, const int* in_sizes, int n_in,
                              void* d_out, int out_size) {
    const float* prior = (const float*)d_in[0];
    const float* cam   = (const float*)d_in[1];
    const float* W1    = (const float*)d_in[2];
    const float* b1    = (const float*)d_in[3];
    const float* W2    = (const float*)d_in[4];
    const float* b2    = (const float*)d_in[5];
    const float* W3    = (const float*)d_in[6];
    const float* b3    = (const float*)d_in[7];
    float* out = (float*)d_out;

    // blockIdx.x = network (fastest-varying) so concurrent blocks cover adjacent n:
    // 24B output chunks of neighboring n merge into full L2 sectors before writeback.
    dim3 grid(N_NET, B_TOT / 1024);
    mlp_kernel<<<grid, 256>>>(prior, cam, W1, b1, W2, b2, W3, b3, out);
}

// round 6
// speedup vs baseline: 8.5764x; 8.5764x over previous
#include <cuda_runtime.h>

#define B_TOT 8192
#define N_NET 722
#define CAMD  10
#define IND   11
#define HD    10
#define LODD  6

using u64 = unsigned long long;

static __device__ __forceinline__ u64 pk2(float a, float b) {
    u64 r; asm("mov.b64 %0, {%1, %2};" : "=l"(r) : "f"(a), "f"(b)); return r;
}
static __device__ __forceinline__ void unpk2(u64 v, float& a, float& b) {
    asm("mov.b64 {%0, %1}, %2;" : "=f"(a), "=f"(b) : "l"(v));
}
// Packed 2-wide fp32 FMA (Blackwell FFMA2) — only reachable via PTX.
static __device__ __forceinline__ u64 ffma2(u64 a, u64 b, u64 c) {
    u64 d; asm("fma.rn.f32x2 %0, %1, %2, %3;" : "=l"(d) : "l"(a), "l"(b), "l"(c)); return d;
}
static __device__ __forceinline__ u64 relu2(u64 v) {
    float a, b; unpk2(v, a, b);
    a = fmaxf(a, 0.0f); b = fmaxf(b, 0.0f);
    return pk2(a, b);
}

// One block: one network n, 512 batch rows (256 threads x 1 f32x2 pair = 2 rows).
// __launch_bounds__(256,3): 85-reg budget -> natural ~70-80 regs fits WITHOUT
// spilling (the (256,4)=64-reg cap spilled accumulators to local and was 5x
// slower). 3 blocks/SM = 24 warps (37.5% occ) hides LDS(29)/FFMA(4) latency.
// Weights in smem pre-duplicated (w,w): one broadcast LDS.64 feeds one FFMA2.
__global__ __launch_bounds__(256, 3) void mlp_kernel(
    const float* __restrict__ prior,  // [B, N]
    const float* __restrict__ cam,    // [B, CAM]
    const float* __restrict__ W1,     // [N, IN, H]
    const float* __restrict__ b1,     // [N, H]
    const float* __restrict__ W2,     // [N, H, H]
    const float* __restrict__ b2,     // [N, H]
    const float* __restrict__ W3,     // [N, H, LOD]
    const float* __restrict__ b3,     // [N, LOD]
    float* __restrict__ out)          // [B, N, LOD]
{
    __shared__ u64 s_w1[IND * HD];
    __shared__ u64 s_b1[HD];
    __shared__ u64 s_w2[HD * HD];
    __shared__ u64 s_b2[HD];
    __shared__ u64 s_w3[HD * LODD];
    __shared__ u64 s_b3[LODD];

    const int n   = blockIdx.x;
    const int tid = threadIdx.x;

    // Cooperative weight stage, duplicated into both f32x2 halves.
    for (int i = tid; i < IND * HD; i += 256) { float v = W1[n * IND * HD + i]; s_w1[i] = pk2(v, v); }
    for (int i = tid; i < HD * HD;  i += 256) { float v = W2[n * HD * HD + i];  s_w2[i] = pk2(v, v); }
    for (int i = tid; i < HD * LODD; i += 256){ float v = W3[n * HD * LODD + i]; s_w3[i] = pk2(v, v); }
    if (tid < HD) {
        float v = b1[n * HD + tid]; s_b1[tid] = pk2(v, v);
        v       = b2[n * HD + tid]; s_b2[tid] = pk2(v, v);
    }
    if (tid < LODD) { float v = b3[n * LODD + tid]; s_b3[tid] = pk2(v, v); }
    __syncthreads();

    const int b0  = blockIdx.y * 512 + tid * 2;  // 2 consecutive batch rows
    const int b1r = b0 + 1;

    // Pack inputs: x[i] = (x_{b0}, x_{b0+1})
    u64 x[IND];
    x[0] = pk2(prior[(size_t)b0 * N_NET + n], prior[(size_t)b1r * N_NET + n]);
    {
        const float2* ca = reinterpret_cast<const float2*>(cam + (size_t)b0 * CAMD);
        const float2* cb = reinterpret_cast<const float2*>(cam + (size_t)b1r * CAMD);
#pragma unroll
        for (int c = 0; c < 5; c++) {
            float2 va = ca[c], vb = cb[c];
            x[1 + 2 * c] = pk2(va.x, vb.x);
            x[2 + 2 * c] = pk2(va.y, vb.y);
        }
    }

    // ---- Layer 1: [IN=11] -> [H=10], ReLU ----
    u64 h1[HD];
#pragma unroll
    for (int h = 0; h < HD; h++) h1[h] = s_b1[h];
#pragma unroll
    for (int i = 0; i < IND; i++) {
#pragma unroll
        for (int h = 0; h < HD; h++)
            h1[h] = ffma2(x[i], s_w1[i * HD + h], h1[h]);
    }
#pragma unroll
    for (int h = 0; h < HD; h++) h1[h] = relu2(h1[h]);

    // ---- Layer 2: [H=10] -> [H=10], ReLU ----
    u64 h2[HD];
#pragma unroll
    for (int k = 0; k < HD; k++) h2[k] = s_b2[k];
#pragma unroll
    for (int h = 0; h < HD; h++) {
#pragma unroll
        for (int k = 0; k < HD; k++)
            h2[k] = ffma2(h1[h], s_w2[h * HD + k], h2[k]);
    }
#pragma unroll
    for (int k = 0; k < HD; k++) h2[k] = relu2(h2[k]);

    // ---- Layer 3: [H=10] -> [LOD=6] ----
    u64 o[LODD];
#pragma unroll
    for (int l = 0; l < LODD; l++) o[l] = s_b3[l];
#pragma unroll
    for (int h = 0; h < HD; h++) {
#pragma unroll
        for (int l = 0; l < LODD; l++)
            o[l] = ffma2(h2[h], s_w3[h * LODD + l], o[l]);
    }

    // ---- Store: out[b][n][0..5] = 24B, 8B-aligned -> 3x st.64 per row ----
    float oa[LODD], ob[LODD];
#pragma unroll
    for (int l = 0; l < LODD; l++) unpk2(o[l], oa[l], ob[l]);
    float2* pa = reinterpret_cast<float2*>(out + ((size_t)b0  * N_NET + n) * LODD);
    float2* pb = reinterpret_cast<float2*>(out + ((size_t)b1r * N_NET + n) * LODD);
    pa[0] = make_float2(oa[0], oa[1]);
    pa[1] = make_float2(oa[2], oa[3]);
    pa[2] = make_float2(oa[4], oa[5]);
    pb[0] = make_float2(ob[0], ob[1]);
    pb[1] = make_float2(ob[2], ob[3]);
    pb[2] = make_float2(ob[4], ob[5]);
}

extern "C" void kernel_launch(void* const* d_in, const int* in_sizes, int n_in,
                              void* d_out, int out_size) {
    const float* prior = (const float*)d_in[0];
    const float* cam   = (const float*)d_in[1];
    const float* W1    = (const float*)d_in[2];
    const float* b1    = (const float*)d_in[3];
    const float* W2    = (const float*)d_in[4];
    const float* b2    = (const float*)d_in[5];
    const float* W3    = (const float*)d_in[6];
    const float* b3    = (const float*)d_in[7];
    float* out = (float*)d_out;

    // blockIdx.x = network (fastest-varying) so concurrent blocks cover adjacent n:
    // 24B output chunks of neighboring n merge into full L2 sectors before writeback.
    dim3 grid(N_NET, B_TOT / 512);
    mlp_kernel<<<grid, 256>>>(prior, cam, W1, b1, W2, b2, W3, b3, out);
}